// round 1
// baseline (speedup 1.0000x reference)
#include <cuda_runtime.h>
#include <cuda_bf16.h>
#include <math.h>

#define SEQ_LEN 16384
#define ENC_H   2048
#define DEC_H   2048

#define K4_CCHUNKS 4          // column chunks of 512 floats each
#define K4_SPLITS  64         // seq splits
#define K4_ROWS    (SEQ_LEN / K4_SPLITS)   // 256 rows per block

// Scratch (device globals — no allocation allowed)
__device__ float g_v[ENC_H];
__device__ float g_scores[SEQ_LEN];
__device__ float g_partial[K4_SPLITS * ENC_H];

// ---------------------------------------------------------------------------
// Kernel 1: v[e] = sum_d W[e,d] * dec[d]    (warp per row)
// ---------------------------------------------------------------------------
__global__ void k1_gemv(const float* __restrict__ W, const float* __restrict__ dec) {
    int gwarp = (blockIdx.x * blockDim.x + threadIdx.x) >> 5;
    int lane  = threadIdx.x & 31;
    if (gwarp >= ENC_H) return;
    const float4* row = reinterpret_cast<const float4*>(W + (size_t)gwarp * DEC_H);
    const float4* d4  = reinterpret_cast<const float4*>(dec);
    float acc = 0.0f;
    #pragma unroll 4
    for (int i = lane; i < DEC_H / 4; i += 32) {
        float4 a = row[i];
        float4 b = __ldg(&d4[i]);
        acc += a.x * b.x + a.y * b.y + a.z * b.z + a.w * b.w;
    }
    #pragma unroll
    for (int o = 16; o > 0; o >>= 1) acc += __shfl_xor_sync(0xffffffffu, acc, o);
    if (lane == 0) g_v[gwarp] = acc;
}

// ---------------------------------------------------------------------------
// Kernel 2: scores[s] = enc[s,:] . v     (block of 128 per row)
// ---------------------------------------------------------------------------
__global__ void k2_scores(const float* __restrict__ enc) {
    int s = blockIdx.x;
    const float4* row = reinterpret_cast<const float4*>(enc + (size_t)s * ENC_H);
    const float4* v4  = reinterpret_cast<const float4*>(g_v);
    float acc = 0.0f;
    #pragma unroll 4
    for (int i = threadIdx.x; i < ENC_H / 4; i += 128) {
        float4 a = row[i];
        float4 b = __ldg(&v4[i]);
        acc += a.x * b.x + a.y * b.y + a.z * b.z + a.w * b.w;
    }
    #pragma unroll
    for (int o = 16; o > 0; o >>= 1) acc += __shfl_xor_sync(0xffffffffu, acc, o);
    __shared__ float red[4];
    int warp = threadIdx.x >> 5;
    int lane = threadIdx.x & 31;
    if (lane == 0) red[warp] = acc;
    __syncthreads();
    if (threadIdx.x == 0)
        g_scores[s] = red[0] + red[1] + red[2] + red[3];
}

// ---------------------------------------------------------------------------
// Kernel 3: in-place softmax over g_scores  (single block, 1024 threads)
// ---------------------------------------------------------------------------
__global__ void k3_softmax() {
    __shared__ float sm[32];
    __shared__ float s_max, s_inv;
    int tid  = threadIdx.x;
    int warp = tid >> 5;
    int lane = tid & 31;

    // pass 1: max
    float m = -INFINITY;
    for (int i = tid; i < SEQ_LEN; i += 1024) m = fmaxf(m, g_scores[i]);
    #pragma unroll
    for (int o = 16; o > 0; o >>= 1) m = fmaxf(m, __shfl_xor_sync(0xffffffffu, m, o));
    if (lane == 0) sm[warp] = m;
    __syncthreads();
    if (warp == 0) {
        float mm = sm[lane];
        #pragma unroll
        for (int o = 16; o > 0; o >>= 1) mm = fmaxf(mm, __shfl_xor_sync(0xffffffffu, mm, o));
        if (lane == 0) s_max = mm;
    }
    __syncthreads();
    float M = s_max;

    // pass 2: sum of exp
    float sum = 0.0f;
    for (int i = tid; i < SEQ_LEN; i += 1024) sum += __expf(g_scores[i] - M);
    #pragma unroll
    for (int o = 16; o > 0; o >>= 1) sum += __shfl_xor_sync(0xffffffffu, sum, o);
    if (lane == 0) sm[warp] = sum;
    __syncthreads();
    if (warp == 0) {
        float ss = sm[lane];
        #pragma unroll
        for (int o = 16; o > 0; o >>= 1) ss += __shfl_xor_sync(0xffffffffu, ss, o);
        if (lane == 0) s_inv = 1.0f / ss;
    }
    __syncthreads();
    float inv = s_inv;

    // pass 3: normalize in place
    for (int i = tid; i < SEQ_LEN; i += 1024)
        g_scores[i] = __expf(g_scores[i] - M) * inv;
}

// ---------------------------------------------------------------------------
// Kernel 4: partial[by, e] = sum_{s in split by} w[s] * enc[s, e]
//   grid (K4_CCHUNKS, K4_SPLITS), 128 threads, float4 per thread (512 cols/blk)
// ---------------------------------------------------------------------------
__global__ void k4_weighted_partial(const float* __restrict__ enc) {
    int t  = threadIdx.x;
    int c4 = blockIdx.x * 128 + t;            // float4 column index [0,512)
    int s0 = blockIdx.y * K4_ROWS;

    const float4* base = reinterpret_cast<const float4*>(enc) + c4;
    float4 acc = make_float4(0.f, 0.f, 0.f, 0.f);
    #pragma unroll 4
    for (int s = s0; s < s0 + K4_ROWS; ++s) {
        float w  = g_scores[s];
        float4 e = base[(size_t)s * (ENC_H / 4)];
        acc.x += w * e.x; acc.y += w * e.y; acc.z += w * e.z; acc.w += w * e.w;
    }
    reinterpret_cast<float4*>(g_partial)[blockIdx.y * (ENC_H / 4) + c4] = acc;
}

// ---------------------------------------------------------------------------
// Kernel 5: out[e] = sum_k partial[k, e]
// ---------------------------------------------------------------------------
__global__ void k5_reduce(float* __restrict__ out) {
    int col = blockIdx.x * 128 + threadIdx.x;
    float s = 0.0f;
    #pragma unroll
    for (int k = 0; k < K4_SPLITS; ++k) s += g_partial[k * ENC_H + col];
    out[col] = s;
}

extern "C" void kernel_launch(void* const* d_in, const int* in_sizes, int n_in,
                              void* d_out, int out_size) {
    const float* enc = (const float*)d_in[0];   // [16384, 2048]
    const float* dec = (const float*)d_in[1];   // [1, 2048]
    const float* W   = (const float*)d_in[2];   // [2048, 2048]
    float* out = (float*)d_out;                 // [1, 2048]

    k1_gemv<<<256, 256>>>(W, dec);                     // 2048 warps, one per row
    k2_scores<<<SEQ_LEN, 128>>>(enc);
    k3_softmax<<<1, 1024>>>();
    dim3 g4(K4_CCHUNKS, K4_SPLITS);
    k4_weighted_partial<<<g4, 128>>>(enc);
    k5_reduce<<<ENC_H / 128, 128>>>(out);
}

// round 2
// speedup vs baseline: 2.0862x; 2.0862x over previous
#include <cuda_runtime.h>
#include <cuda_bf16.h>
#include <math.h>

#define SEQ_LEN 16384
#define ENC_H   2048
#define DEC_H   2048

#define THREADS 256
#define NBLK    512
#define ROWS_PER_BLK (SEQ_LEN / NBLK)   // 32
#define RB      4                        // rows per batch (register-resident)
#define BCHUNK  32                       // blocks summed per combine block
#define NP2     (NBLK / BCHUNK)          // 16

// Scratch (device globals — no allocation allowed)
__device__ float g_v[ENC_H];
__device__ float g_ctx[NBLK * ENC_H];    // per-block partial contexts (4 MB)
__device__ float g_m[NBLK];
__device__ float g_z[NBLK];
__device__ float g_scale[NBLK];
__device__ float g_p2[NP2 * ENC_H];

// ---------------------------------------------------------------------------
// Kernel 1: v[e] = sum_d W[e,d] * dec[d]    (warp per row)
// ---------------------------------------------------------------------------
__global__ void k1_gemv(const float* __restrict__ W, const float* __restrict__ dec) {
    int gwarp = (blockIdx.x * blockDim.x + threadIdx.x) >> 5;
    int lane  = threadIdx.x & 31;
    if (gwarp >= ENC_H) return;
    const float4* row = reinterpret_cast<const float4*>(W + (size_t)gwarp * DEC_H);
    const float4* d4  = reinterpret_cast<const float4*>(dec);
    float acc = 0.0f;
    #pragma unroll 4
    for (int i = lane; i < DEC_H / 4; i += 32) {
        float4 a = row[i];
        float4 b = __ldg(&d4[i]);
        acc += a.x * b.x + a.y * b.y + a.z * b.z + a.w * b.w;
    }
    #pragma unroll
    for (int o = 16; o > 0; o >>= 1) acc += __shfl_xor_sync(0xffffffffu, acc, o);
    if (lane == 0) g_v[gwarp] = acc;
}

// ---------------------------------------------------------------------------
// Kernel A: fused scores + online softmax + weighted accumulate (one enc pass)
//   512 blocks x 256 threads; each block owns 32 rows, each thread owns 8 cols
// ---------------------------------------------------------------------------
__global__ __launch_bounds__(THREADS) void kA_fused(const float* __restrict__ enc) {
    __shared__ float s_red[8][RB];
    int t    = threadIdx.x;
    int warp = t >> 5;
    int lane = t & 31;
    int s0   = blockIdx.x * ROWS_PER_BLK;

    const float4* v4 = reinterpret_cast<const float4*>(g_v);
    float4 v0 = v4[t];
    float4 v1 = v4[t + THREADS];

    float4 a0 = make_float4(0.f, 0.f, 0.f, 0.f);
    float4 a1 = make_float4(0.f, 0.f, 0.f, 0.f);
    float m = -INFINITY, z = 0.0f;

    for (int b = 0; b < ROWS_PER_BLK; b += RB) {
        float4 r0[RB], r1[RB];
        float  d[RB];
        #pragma unroll
        for (int r = 0; r < RB; ++r) {
            const float4* row = reinterpret_cast<const float4*>(
                enc + (size_t)(s0 + b + r) * ENC_H);
            r0[r] = row[t];
            r1[r] = row[t + THREADS];
            d[r] = r0[r].x * v0.x + r0[r].y * v0.y + r0[r].z * v0.z + r0[r].w * v0.w
                 + r1[r].x * v1.x + r1[r].y * v1.y + r1[r].z * v1.z + r1[r].w * v1.w;
        }
        // block reduce RB dots
        #pragma unroll
        for (int r = 0; r < RB; ++r) {
            float x = d[r];
            #pragma unroll
            for (int o = 16; o > 0; o >>= 1) x += __shfl_xor_sync(0xffffffffu, x, o);
            if (lane == 0) s_red[warp][r] = x;
        }
        __syncthreads();
        float sc[RB];
        #pragma unroll
        for (int r = 0; r < RB; ++r) {
            float x = 0.0f;
            #pragma unroll
            for (int w = 0; w < 8; ++w) x += s_red[w][r];
            sc[r] = x;
        }
        __syncthreads();   // protect smem before next batch reuses it

        // online softmax update (all threads compute identical m/z)
        float nm = m;
        #pragma unroll
        for (int r = 0; r < RB; ++r) nm = fmaxf(nm, sc[r]);
        float f = __expf(m - nm);   // first iter: exp(-inf)=0, acc/z already 0
        a0.x *= f; a0.y *= f; a0.z *= f; a0.w *= f;
        a1.x *= f; a1.y *= f; a1.z *= f; a1.w *= f;
        z *= f;
        #pragma unroll
        for (int r = 0; r < RB; ++r) {
            float w = __expf(sc[r] - nm);
            z += w;
            a0.x += w * r0[r].x; a0.y += w * r0[r].y;
            a0.z += w * r0[r].z; a0.w += w * r0[r].w;
            a1.x += w * r1[r].x; a1.y += w * r1[r].y;
            a1.z += w * r1[r].z; a1.w += w * r1[r].w;
        }
        m = nm;
    }

    float4* ctx = reinterpret_cast<float4*>(g_ctx + (size_t)blockIdx.x * ENC_H);
    ctx[t] = a0;
    ctx[t + THREADS] = a1;
    if (t == 0) { g_m[blockIdx.x] = m; g_z[blockIdx.x] = z; }
}

// ---------------------------------------------------------------------------
// Kernel B1: global max/sum across blocks -> per-block scale (1 block, 512 thr)
// ---------------------------------------------------------------------------
__global__ void kB1_scale() {
    __shared__ float sm[16];
    __shared__ float s_M, s_invZ;
    int t = threadIdx.x;           // 512 threads == NBLK
    int warp = t >> 5, lane = t & 31;

    float mv = g_m[t];
    float x = mv;
    #pragma unroll
    for (int o = 16; o > 0; o >>= 1) x = fmaxf(x, __shfl_xor_sync(0xffffffffu, x, o));
    if (lane == 0) sm[warp] = x;
    __syncthreads();
    if (warp == 0) {
        float y = (lane < 16) ? sm[lane] : -INFINITY;
        #pragma unroll
        for (int o = 16; o > 0; o >>= 1) y = fmaxf(y, __shfl_xor_sync(0xffffffffu, y, o));
        if (lane == 0) s_M = y;
    }
    __syncthreads();
    float M = s_M;

    float e = __expf(mv - M);
    float zz = g_z[t] * e;
    float s = zz;
    #pragma unroll
    for (int o = 16; o > 0; o >>= 1) s += __shfl_xor_sync(0xffffffffu, s, o);
    if (lane == 0) sm[warp] = s;
    __syncthreads();
    if (warp == 0) {
        float y = (lane < 16) ? sm[lane] : 0.0f;
        #pragma unroll
        for (int o = 16; o > 0; o >>= 1) y += __shfl_xor_sync(0xffffffffu, y, o);
        if (lane == 0) s_invZ = 1.0f / y;
    }
    __syncthreads();
    g_scale[t] = e * s_invZ;
}

// ---------------------------------------------------------------------------
// Kernel B2: p2[by, col] = sum over 32 blocks of scale[b] * ctx[b, col]
//   grid (8, 16) x 256 threads
// ---------------------------------------------------------------------------
__global__ void kB2_partial() {
    int col = blockIdx.x * THREADS + threadIdx.x;
    int b0  = blockIdx.y * BCHUNK;
    float acc = 0.0f;
    #pragma unroll 8
    for (int b = b0; b < b0 + BCHUNK; ++b)
        acc += g_scale[b] * g_ctx[(size_t)b * ENC_H + col];
    g_p2[blockIdx.y * ENC_H + col] = acc;
}

// ---------------------------------------------------------------------------
// Kernel B3: out[col] = sum over 16 partials
// ---------------------------------------------------------------------------
__global__ void kB3_final(float* __restrict__ out) {
    int col = blockIdx.x * THREADS + threadIdx.x;
    float s = 0.0f;
    #pragma unroll
    for (int k = 0; k < NP2; ++k) s += g_p2[k * ENC_H + col];
    out[col] = s;
}

extern "C" void kernel_launch(void* const* d_in, const int* in_sizes, int n_in,
                              void* d_out, int out_size) {
    const float* enc = (const float*)d_in[0];   // [16384, 2048]
    const float* dec = (const float*)d_in[1];   // [1, 2048]
    const float* W   = (const float*)d_in[2];   // [2048, 2048]
    float* out = (float*)d_out;                 // [1, 2048]

    k1_gemv<<<256, 256>>>(W, dec);
    kA_fused<<<NBLK, THREADS>>>(enc);
    kB1_scale<<<1, NBLK>>>();
    dim3 g2(ENC_H / THREADS, NP2);
    kB2_partial<<<g2, THREADS>>>();
    kB3_final<<<ENC_H / THREADS, THREADS>>>(out);
}

// round 3
// speedup vs baseline: 2.2831x; 1.0944x over previous
#include <cuda_runtime.h>
#include <cuda_bf16.h>
#include <math.h>

#define SEQ_LEN 16384
#define ENC_H   2048
#define DEC_H   2048

#define THREADS 256
#define NBLK    512
#define ROWS_PER_BLK (SEQ_LEN / NBLK)   // 32
#define RB      4                        // rows per batch (register-resident)

// Scratch (device globals — no allocation allowed)
__device__ float g_v[ENC_H];
__device__ float g_ctx[NBLK * ENC_H];    // per-block partial contexts (4 MB)
__device__ float g_m[NBLK];
__device__ float g_z[NBLK];

// ---------------------------------------------------------------------------
// Kernel 1: v[e] = sum_d W[e,d] * dec[d]    (warp per row)
// ---------------------------------------------------------------------------
__global__ void k1_gemv(const float* __restrict__ W, const float* __restrict__ dec) {
    int gwarp = (blockIdx.x * blockDim.x + threadIdx.x) >> 5;
    int lane  = threadIdx.x & 31;
    if (gwarp >= ENC_H) return;
    const float4* row = reinterpret_cast<const float4*>(W + (size_t)gwarp * DEC_H);
    const float4* d4  = reinterpret_cast<const float4*>(dec);
    float acc = 0.0f;
    #pragma unroll 4
    for (int i = lane; i < DEC_H / 4; i += 32) {
        float4 a = row[i];
        float4 b = __ldg(&d4[i]);
        acc += a.x * b.x + a.y * b.y + a.z * b.z + a.w * b.w;
    }
    #pragma unroll
    for (int o = 16; o > 0; o >>= 1) acc += __shfl_xor_sync(0xffffffffu, acc, o);
    if (lane == 0) g_v[gwarp] = acc;
}

// ---------------------------------------------------------------------------
// Kernel A: fused scores + online softmax + weighted accumulate (one enc pass)
//   512 blocks x 256 threads; each block owns 32 rows, each thread owns 8 cols
// ---------------------------------------------------------------------------
__global__ __launch_bounds__(THREADS) void kA_fused(const float* __restrict__ enc) {
    __shared__ float s_red[8][RB];
    int t    = threadIdx.x;
    int warp = t >> 5;
    int lane = t & 31;
    int s0   = blockIdx.x * ROWS_PER_BLK;

    const float4* v4 = reinterpret_cast<const float4*>(g_v);
    float4 v0 = v4[t];
    float4 v1 = v4[t + THREADS];

    float4 a0 = make_float4(0.f, 0.f, 0.f, 0.f);
    float4 a1 = make_float4(0.f, 0.f, 0.f, 0.f);
    float m = -INFINITY, z = 0.0f;

    for (int b = 0; b < ROWS_PER_BLK; b += RB) {
        float4 r0[RB], r1[RB];
        float  d[RB];
        #pragma unroll
        for (int r = 0; r < RB; ++r) {
            const float4* row = reinterpret_cast<const float4*>(
                enc + (size_t)(s0 + b + r) * ENC_H);
            r0[r] = row[t];
            r1[r] = row[t + THREADS];
            d[r] = r0[r].x * v0.x + r0[r].y * v0.y + r0[r].z * v0.z + r0[r].w * v0.w
                 + r1[r].x * v1.x + r1[r].y * v1.y + r1[r].z * v1.z + r1[r].w * v1.w;
        }
        #pragma unroll
        for (int r = 0; r < RB; ++r) {
            float x = d[r];
            #pragma unroll
            for (int o = 16; o > 0; o >>= 1) x += __shfl_xor_sync(0xffffffffu, x, o);
            if (lane == 0) s_red[warp][r] = x;
        }
        __syncthreads();
        float sc[RB];
        #pragma unroll
        for (int r = 0; r < RB; ++r) {
            float x = 0.0f;
            #pragma unroll
            for (int w = 0; w < 8; ++w) x += s_red[w][r];
            sc[r] = x;
        }
        __syncthreads();

        float nm = m;
        #pragma unroll
        for (int r = 0; r < RB; ++r) nm = fmaxf(nm, sc[r]);
        float f = __expf(m - nm);
        a0.x *= f; a0.y *= f; a0.z *= f; a0.w *= f;
        a1.x *= f; a1.y *= f; a1.z *= f; a1.w *= f;
        z *= f;
        #pragma unroll
        for (int r = 0; r < RB; ++r) {
            float w = __expf(sc[r] - nm);
            z += w;
            a0.x += w * r0[r].x; a0.y += w * r0[r].y;
            a0.z += w * r0[r].z; a0.w += w * r0[r].w;
            a1.x += w * r1[r].x; a1.y += w * r1[r].y;
            a1.z += w * r1[r].z; a1.w += w * r1[r].w;
        }
        m = nm;
    }

    float4* ctx = reinterpret_cast<float4*>(g_ctx + (size_t)blockIdx.x * ENC_H);
    ctx[t] = a0;
    ctx[t + THREADS] = a1;
    if (t == 0) { g_m[blockIdx.x] = m; g_z[blockIdx.x] = z; }
}

// ---------------------------------------------------------------------------
// Kernel B: single-kernel combine.
//   grid 128 x 128 threads. Each block:
//   phase 1: redundantly compute M, Z and per-block e_b = exp(m_b - M) (smem)
//   phase 2: 4 warps, each owns one float4-column; lanes stride 512 rows
//            (16 float4 loads in flight per lane), shuffle-reduce, write out.
// ---------------------------------------------------------------------------
__global__ __launch_bounds__(128) void kB_combine(float* __restrict__ out) {
    __shared__ float s_e[NBLK];
    __shared__ float s_red[4];
    __shared__ float s_M, s_invZ;
    int t    = threadIdx.x;
    int warp = t >> 5;
    int lane = t & 31;

    // ---- phase 1: global max M ----
    float m = fmaxf(g_m[t], fmaxf(g_m[t + 128], fmaxf(g_m[t + 256], g_m[t + 384])));
    #pragma unroll
    for (int o = 16; o > 0; o >>= 1) m = fmaxf(m, __shfl_xor_sync(0xffffffffu, m, o));
    if (lane == 0) s_red[warp] = m;
    __syncthreads();
    if (t == 0)
        s_M = fmaxf(fmaxf(s_red[0], s_red[1]), fmaxf(s_red[2], s_red[3]));
    __syncthreads();
    float M = s_M;

    // ---- e_b and Z ----
    float zsum = 0.0f;
    #pragma unroll
    for (int i = t; i < NBLK; i += 128) {
        float e = __expf(g_m[i] - M);
        s_e[i] = e;
        zsum += e * g_z[i];
    }
    #pragma unroll
    for (int o = 16; o > 0; o >>= 1) zsum += __shfl_xor_sync(0xffffffffu, zsum, o);
    __syncthreads();               // s_red reuse ordering
    if (lane == 0) s_red[warp] = zsum;
    __syncthreads();
    if (t == 0)
        s_invZ = 1.0f / (s_red[0] + s_red[1] + s_red[2] + s_red[3]);
    __syncthreads();

    // ---- phase 2: reduce 512 partial contexts for this block's 4 columns ----
    int col4 = blockIdx.x * 4 + warp;           // [0, 512)
    const float4* ctx = reinterpret_cast<const float4*>(g_ctx);
    float4 acc = make_float4(0.f, 0.f, 0.f, 0.f);
    #pragma unroll
    for (int b = lane; b < NBLK; b += 32) {
        float w  = s_e[b];
        float4 c = ctx[(size_t)b * (ENC_H / 4) + col4];
        acc.x += w * c.x; acc.y += w * c.y; acc.z += w * c.z; acc.w += w * c.w;
    }
    #pragma unroll
    for (int o = 16; o > 0; o >>= 1) {
        acc.x += __shfl_xor_sync(0xffffffffu, acc.x, o);
        acc.y += __shfl_xor_sync(0xffffffffu, acc.y, o);
        acc.z += __shfl_xor_sync(0xffffffffu, acc.z, o);
        acc.w += __shfl_xor_sync(0xffffffffu, acc.w, o);
    }
    if (lane == 0) {
        float inv = s_invZ;
        float4 r = make_float4(acc.x * inv, acc.y * inv, acc.z * inv, acc.w * inv);
        reinterpret_cast<float4*>(out)[col4] = r;
    }
}

extern "C" void kernel_launch(void* const* d_in, const int* in_sizes, int n_in,
                              void* d_out, int out_size) {
    const float* enc = (const float*)d_in[0];   // [16384, 2048]
    const float* dec = (const float*)d_in[1];   // [1, 2048]
    const float* W   = (const float*)d_in[2];   // [2048, 2048]
    float* out = (float*)d_out;                 // [1, 2048]

    k1_gemv<<<256, 256>>>(W, dec);
    kA_fused<<<NBLK, THREADS>>>(enc);
    kB_combine<<<128, 128>>>(out);
}

// round 5
// speedup vs baseline: 2.2898x; 1.0029x over previous
#include <cuda_runtime.h>
#include <cuda_bf16.h>
#include <math.h>

#define SEQ_LEN 16384
#define ENC_H   2048
#define DEC_H   2048

#define THREADS 256
#define NBLK    512
#define ROWS_PER_BLK (SEQ_LEN / NBLK)   // 32
#define RB      4                        // rows per batch (register-resident)
#define NBATCH  (ROWS_PER_BLK / RB)      // 8

// Scratch (device globals — no allocation allowed)
__device__ float g_v[ENC_H];
__device__ float g_ctx[NBLK * ENC_H];    // per-block partial contexts (4 MB)
__device__ float g_m[NBLK];
__device__ float g_z[NBLK];

// ---------------------------------------------------------------------------
// Kernel 1: v[e] = sum_d W[e,d] * dec[d]   (warp per row, FULL unroll: 16
// outstanding LDG.128 per lane -> latency fully hidden, LTS-cap bound)
// ---------------------------------------------------------------------------
__global__ __launch_bounds__(256) void k1_gemv(const float* __restrict__ W,
                                               const float* __restrict__ dec) {
    int gwarp = (blockIdx.x * blockDim.x + threadIdx.x) >> 5;
    int lane  = threadIdx.x & 31;
    const float4* row = reinterpret_cast<const float4*>(W + (size_t)gwarp * DEC_H);
    const float4* d4  = reinterpret_cast<const float4*>(dec);
    float4 a[16], b[16];
    #pragma unroll
    for (int i = 0; i < 16; ++i) {
        a[i] = row[lane + 32 * i];
        b[i] = __ldg(&d4[lane + 32 * i]);
    }
    float acc = 0.0f;
    #pragma unroll
    for (int i = 0; i < 16; ++i)
        acc += a[i].x * b[i].x + a[i].y * b[i].y + a[i].z * b[i].z + a[i].w * b[i].w;
    #pragma unroll
    for (int o = 16; o > 0; o >>= 1) acc += __shfl_xor_sync(0xffffffffu, acc, o);
    if (lane == 0) g_v[gwarp] = acc;
}

// ---------------------------------------------------------------------------
// Kernel A: fused scores + online softmax + weighted accumulate, software-
// pipelined: batch i+1's loads are issued before batch i's reduction so DRAM
// latency overlaps the shuffle/smem/exp work.
// ---------------------------------------------------------------------------
__global__ __launch_bounds__(THREADS) void kA_fused(const float* __restrict__ enc) {
    __shared__ float s_red[8][RB];
    int t    = threadIdx.x;
    int warp = t >> 5;
    int lane = t & 31;
    int s0   = blockIdx.x * ROWS_PER_BLK;

    const float4* v4 = reinterpret_cast<const float4*>(g_v);
    float4 v0 = v4[t];
    float4 v1 = v4[t + THREADS];

    float4 a0 = make_float4(0.f, 0.f, 0.f, 0.f);
    float4 a1 = make_float4(0.f, 0.f, 0.f, 0.f);
    float m = -INFINITY, z = 0.0f;

    float4 rb0[2][RB], rb1[2][RB];

    // prefetch batch 0
    #pragma unroll
    for (int r = 0; r < RB; ++r) {
        const float4* row = reinterpret_cast<const float4*>(
            enc + (size_t)(s0 + r) * ENC_H);
        rb0[0][r] = row[t];
        rb1[0][r] = row[t + THREADS];
    }

    #pragma unroll
    for (int bb = 0; bb < NBATCH; ++bb) {
        const int p = bb & 1, q = p ^ 1;

        // issue next batch's loads first (overlap with reduction below)
        if (bb + 1 < NBATCH) {
            #pragma unroll
            for (int r = 0; r < RB; ++r) {
                const float4* row = reinterpret_cast<const float4*>(
                    enc + (size_t)(s0 + (bb + 1) * RB + r) * ENC_H);
                rb0[q][r] = row[t];
                rb1[q][r] = row[t + THREADS];
            }
        }

        // dots for current batch
        float d[RB];
        #pragma unroll
        for (int r = 0; r < RB; ++r) {
            float4 x0 = rb0[p][r], x1 = rb1[p][r];
            d[r] = x0.x * v0.x + x0.y * v0.y + x0.z * v0.z + x0.w * v0.w
                 + x1.x * v1.x + x1.y * v1.y + x1.z * v1.z + x1.w * v1.w;
        }
        #pragma unroll
        for (int r = 0; r < RB; ++r) {
            float x = d[r];
            #pragma unroll
            for (int o = 16; o > 0; o >>= 1) x += __shfl_xor_sync(0xffffffffu, x, o);
            if (lane == 0) s_red[warp][r] = x;
        }
        __syncthreads();
        float sc[RB];
        #pragma unroll
        for (int r = 0; r < RB; ++r) {
            float x = 0.0f;
            #pragma unroll
            for (int w = 0; w < 8; ++w) x += s_red[w][r];
            sc[r] = x;
        }
        __syncthreads();

        // online softmax update
        float nm = m;
        #pragma unroll
        for (int r = 0; r < RB; ++r) nm = fmaxf(nm, sc[r]);
        float f = __expf(m - nm);
        a0.x *= f; a0.y *= f; a0.z *= f; a0.w *= f;
        a1.x *= f; a1.y *= f; a1.z *= f; a1.w *= f;
        z *= f;
        #pragma unroll
        for (int r = 0; r < RB; ++r) {
            float w = __expf(sc[r] - nm);
            z += w;
            float4 x0 = rb0[p][r], x1 = rb1[p][r];
            a0.x += w * x0.x; a0.y += w * x0.y; a0.z += w * x0.z; a0.w += w * x0.w;
            a1.x += w * x1.x; a1.y += w * x1.y; a1.z += w * x1.z; a1.w += w * x1.w;
        }
        m = nm;
    }

    float4* ctx = reinterpret_cast<float4*>(g_ctx + (size_t)blockIdx.x * ENC_H);
    ctx[t] = a0;
    ctx[t + THREADS] = a1;
    if (t == 0) { g_m[blockIdx.x] = m; g_z[blockIdx.x] = z; }
}

// ---------------------------------------------------------------------------
// Kernel B: single-kernel combine (M, Z, weighted 512-way reduction -> out)
// ---------------------------------------------------------------------------
__global__ __launch_bounds__(128) void kB_combine(float* __restrict__ out) {
    __shared__ float s_e[NBLK];
    __shared__ float s_red[4];
    __shared__ float s_M, s_invZ;
    int t    = threadIdx.x;
    int warp = t >> 5;
    int lane = t & 31;

    float m = fmaxf(g_m[t], fmaxf(g_m[t + 128], fmaxf(g_m[t + 256], g_m[t + 384])));
    #pragma unroll
    for (int o = 16; o > 0; o >>= 1) m = fmaxf(m, __shfl_xor_sync(0xffffffffu, m, o));
    if (lane == 0) s_red[warp] = m;
    __syncthreads();
    if (t == 0)
        s_M = fmaxf(fmaxf(s_red[0], s_red[1]), fmaxf(s_red[2], s_red[3]));
    __syncthreads();
    float M = s_M;

    float zsum = 0.0f;
    #pragma unroll
    for (int i = t; i < NBLK; i += 128) {
        float e = __expf(g_m[i] - M);
        s_e[i] = e;
        zsum += e * g_z[i];
    }
    #pragma unroll
    for (int o = 16; o > 0; o >>= 1) zsum += __shfl_xor_sync(0xffffffffu, zsum, o);
    __syncthreads();
    if (lane == 0) s_red[warp] = zsum;
    __syncthreads();
    if (t == 0)
        s_invZ = 1.0f / (s_red[0] + s_red[1] + s_red[2] + s_red[3]);
    __syncthreads();

    int col4 = blockIdx.x * 4 + warp;
    const float4* ctx = reinterpret_cast<const float4*>(g_ctx);
    float4 acc = make_float4(0.f, 0.f, 0.f, 0.f);
    #pragma unroll
    for (int b = lane; b < NBLK; b += 32) {
        float w  = s_e[b];
        float4 c = ctx[(size_t)b * (ENC_H / 4) + col4];
        acc.x += w * c.x; acc.y += w * c.y; acc.z += w * c.z; acc.w += w * c.w;
    }
    #pragma unroll
    for (int o = 16; o > 0; o >>= 1) {
        acc.x += __shfl_xor_sync(0xffffffffu, acc.x, o);
        acc.y += __shfl_xor_sync(0xffffffffu, acc.y, o);
        acc.z += __shfl_xor_sync(0xffffffffu, acc.z, o);
        acc.w += __shfl_xor_sync(0xffffffffu, acc.w, o);
    }
    if (lane == 0) {
        float inv = s_invZ;
        float4 r = make_float4(acc.x * inv, acc.y * inv, acc.z * inv, acc.w * inv);
        reinterpret_cast<float4*>(out)[col4] = r;
    }
}

extern "C" void kernel_launch(void* const* d_in, const int* in_sizes, int n_in,
                              void* d_out, int out_size) {
    const float* enc = (const float*)d_in[0];   // [16384, 2048]
    const float* dec = (const float*)d_in[1];   // [1, 2048]
    const float* W   = (const float*)d_in[2];   // [2048, 2048]
    float* out = (float*)d_out;                 // [1, 2048]

    k1_gemv<<<256, 256>>>(W, dec);
    kA_fused<<<NBLK, THREADS>>>(enc);
    kB_combine<<<128, 128>>>(out);
}